// round 14
// baseline (speedup 1.0000x reference)
#include <cuda_runtime.h>

// 2-layer GCN: R13 structure; GEMMs at 6 rows/thread (natural ~88 regs -> ~24 warps/SM).

#define N_NODES 50000
#define DIM_IN 64
#define DIM_HID 128
#define CAP 128

typedef unsigned long long u64;

__device__ __forceinline__ u64 pk(float v) {
    u64 r; asm("mov.b64 %0, {%1, %1};" : "=l"(r) : "f"(v)); return r;
}
__device__ __forceinline__ void fma2(u64& d, u64 a, u64 b) {
    asm("fma.rn.f32x2 %0, %1, %2, %3;" : "=l"(d) : "l"(a), "l"(b), "l"(d));
}
__device__ __forceinline__ float2 up(u64 v) {
    float2 f; asm("mov.b64 {%0, %1}, %2;" : "=f"(f.x), "=f"(f.y) : "l"(v)); return f;
}

__device__ int   g_cnt[N_NODES];
__device__ int   g_bucket[N_NODES * CAP];
__device__ float g_dinv[N_NODES];
__device__ float g_y   [N_NODES * DIM_IN];
__device__ float g_z   [N_NODES * DIM_IN];
__device__ float g_h   [N_NODES * DIM_HID];
__device__ float g_y2  [N_NODES * DIM_IN];

// ---------------- build ----------------
__global__ void k_place(const int* __restrict__ src, const int* __restrict__ dst, int e) {
    int i = blockIdx.x * blockDim.x + threadIdx.x;
    if (i < e) {
        int d = dst[i];
        int pos = atomicAdd(&g_cnt[d], 1);
        g_bucket[d * CAP + pos] = src[i];
    }
}

// ---------------- prescale: y = dinv*x ; materialize dinv ----------------
__global__ void k_prescale(const float* __restrict__ x, float* __restrict__ y, int n) {
    int idx = blockIdx.x * blockDim.x + threadIdx.x;  // n*16
    if (idx >= n * 16) return;
    int i = idx >> 4;
    float d = rsqrtf((float)g_cnt[i] + 1.0f);
    if ((idx & 15) == 0) g_dinv[i] = d;
    float4 v = reinterpret_cast<const float4*>(x)[idx];
    float4 o = {d * v.x, d * v.y, d * v.z, d * v.w};
    reinterpret_cast<float4*>(y)[idx] = o;
}

// ---------------- gather aggregation (R5 core) ----------------
template <bool FINISH>
__global__ void __launch_bounds__(512, 3) k_agg(
        const float* __restrict__ F, float* __restrict__ O,
        const float* __restrict__ bias, int n) {
    int node = blockIdx.x * 32 + threadIdx.y;
    if (node >= n) return;
    int lane = threadIdx.x;
    const float4* F4 = reinterpret_cast<const float4*>(F);
    const int4* cols4 = reinterpret_cast<const int4*>(g_bucket + node * CAP);
    int cnt = g_cnt[node];

    float4 acc = F4[node * 16 + lane];  // self term
    int j = 0;
    for (; j + 4 <= cnt; j += 4) {
        int4 c = __ldg(&cols4[j >> 2]);
        float4 u0 = F4[c.x * 16 + lane];
        float4 u1 = F4[c.y * 16 + lane];
        float4 u2 = F4[c.z * 16 + lane];
        float4 u3 = F4[c.w * 16 + lane];
        acc.x += (u0.x + u1.x) + (u2.x + u3.x);
        acc.y += (u0.y + u1.y) + (u2.y + u3.y);
        acc.z += (u0.z + u1.z) + (u2.z + u3.z);
        acc.w += (u0.w + u1.w) + (u2.w + u3.w);
    }
    if (j < cnt) {
        int4 c = __ldg(&cols4[j >> 2]);
        int rem = cnt - j;
        float4 u0 = F4[c.x * 16 + lane];
        acc.x += u0.x; acc.y += u0.y; acc.z += u0.z; acc.w += u0.w;
        if (rem > 1) {
            float4 u1 = F4[c.y * 16 + lane];
            acc.x += u1.x; acc.y += u1.y; acc.z += u1.z; acc.w += u1.w;
        }
        if (rem > 2) {
            float4 u2 = F4[c.z * 16 + lane];
            acc.x += u2.x; acc.y += u2.y; acc.z += u2.z; acc.w += u2.w;
        }
    }
    float4 o;
    if (FINISH) {
        float di = g_dinv[node];
        float4 bb = reinterpret_cast<const float4*>(bias)[lane];
        o.x = fmaf(di, acc.x, bb.x);
        o.y = fmaf(di, acc.y, bb.y);
        o.z = fmaf(di, acc.z, bb.z);
        o.w = fmaf(di, acc.w, bb.w);
    } else {
        o = acc;
    }
    reinterpret_cast<float4*>(O)[node * 16 + lane] = o;
}

// ---------------- GEMM1: h = relu(b1 + dinv[r]*(z@W1))  [n,64]x[64,128] ----------------
// block (32,8), 6 rows/thread => 48 rows/block. f32x2 FMA.
__global__ void __launch_bounds__(256) k_gemm1(
        const float* __restrict__ Z, const float* __restrict__ W,
        const float* __restrict__ b, float* __restrict__ H, int n) {
    __shared__ float Ws[64 * 128];
    int tid = threadIdx.y * 32 + threadIdx.x;
    {
        const float4* w4 = reinterpret_cast<const float4*>(W);
        float4* s4 = reinterpret_cast<float4*>(Ws);
        for (int i = tid; i < 64 * 128 / 4; i += 256) s4[i] = w4[i];
    }
    __syncthreads();
    int tx = threadIdx.x;
    int r0 = blockIdx.x * 48 + threadIdx.y * 6;
    int rr[6];
    #pragma unroll
    for (int q = 0; q < 6; q++) rr[q] = min(r0 + q, n - 1);
    const float4* A4 = reinterpret_cast<const float4*>(Z);
    const ulonglong2* ws2 = reinterpret_cast<const ulonglong2*>(Ws);
    u64 acc[6][2] = {};
    #pragma unroll
    for (int k4 = 0; k4 < 16; k4++) {
        float va[6][4];
        #pragma unroll
        for (int q = 0; q < 6; q++) {
            float4 v = A4[rr[q] * 16 + k4];
            va[q][0] = v.x; va[q][1] = v.y; va[q][2] = v.z; va[q][3] = v.w;
        }
        #pragma unroll
        for (int s = 0; s < 4; s++) {
            ulonglong2 w = ws2[(4 * k4 + s) * 32 + tx];
            #pragma unroll
            for (int q = 0; q < 6; q++) {
                u64 m = pk(va[q][s]);
                fma2(acc[q][0], m, w.x);
                fma2(acc[q][1], m, w.y);
            }
        }
    }
    float4 bb = reinterpret_cast<const float4*>(b)[tx];
    float4* H4 = reinterpret_cast<float4*>(H);
    #pragma unroll
    for (int q = 0; q < 6; q++) {
        int r = r0 + q;
        if (r < n) {
            float s = g_dinv[r];
            float2 lo = up(acc[q][0]);
            float2 hi = up(acc[q][1]);
            float4 o;
            o.x = fmaxf(fmaf(s, lo.x, bb.x), 0.f);
            o.y = fmaxf(fmaf(s, lo.y, bb.y), 0.f);
            o.z = fmaxf(fmaf(s, hi.x, bb.z), 0.f);
            o.w = fmaxf(fmaf(s, hi.y, bb.w), 0.f);
            H4[(size_t)r * 32 + tx] = o;
        }
    }
}

// ---------------- GEMM2: y2 = dinv[r]*(h@W2)  [n,128]x[128,64] ----------------
// block (16,16), 6 rows/thread => 96 rows/block.
__global__ void __launch_bounds__(256) k_gemm2(
        const float* __restrict__ H, const float* __restrict__ W,
        float* __restrict__ Y2, int n) {
    __shared__ float Ws[128 * 64];
    int tid = threadIdx.y * 16 + threadIdx.x;
    {
        const float4* w4 = reinterpret_cast<const float4*>(W);
        float4* s4 = reinterpret_cast<float4*>(Ws);
        for (int i = tid; i < 128 * 64 / 4; i += 256) s4[i] = w4[i];
    }
    __syncthreads();
    int tx = threadIdx.x;
    int r0 = blockIdx.x * 96 + threadIdx.y * 6;
    int rr[6];
    #pragma unroll
    for (int q = 0; q < 6; q++) rr[q] = min(r0 + q, n - 1);
    const float4* A4 = reinterpret_cast<const float4*>(H);
    const ulonglong2* ws2 = reinterpret_cast<const ulonglong2*>(Ws);
    u64 acc[6][2] = {};
    #pragma unroll
    for (int k4 = 0; k4 < 32; k4++) {
        float va[6][4];
        #pragma unroll
        for (int q = 0; q < 6; q++) {
            float4 v = A4[rr[q] * 32 + k4];
            va[q][0] = v.x; va[q][1] = v.y; va[q][2] = v.z; va[q][3] = v.w;
        }
        #pragma unroll
        for (int s = 0; s < 4; s++) {
            ulonglong2 w = ws2[(4 * k4 + s) * 16 + tx];
            #pragma unroll
            for (int q = 0; q < 6; q++) {
                u64 m = pk(va[q][s]);
                fma2(acc[q][0], m, w.x);
                fma2(acc[q][1], m, w.y);
            }
        }
    }
    float4* Y4 = reinterpret_cast<float4*>(Y2);
    #pragma unroll
    for (int q = 0; q < 6; q++) {
        int r = r0 + q;
        if (r < n) {
            float s = g_dinv[r];
            float2 lo = up(acc[q][0]);
            float2 hi = up(acc[q][1]);
            float4 o = {s * lo.x, s * lo.y, s * hi.x, s * hi.y};
            Y4[(size_t)r * 16 + tx] = o;
        }
    }
}

extern "C" void kernel_launch(void* const* d_in, const int* in_sizes, int n_in,
                              void* d_out, int out_size) {
    const float* x  = (const float*)d_in[0];
    const int*   ei = (const int*)  d_in[1];
    const float* W1 = (const float*)d_in[2];
    const float* b1 = (const float*)d_in[3];
    const float* W2 = (const float*)d_in[4];
    const float* b2 = (const float*)d_in[5];
    float* out = (float*)d_out;

    int n = in_sizes[0] / DIM_IN;   // 50000
    int e = in_sizes[1] / 2;        // 800000
    const int* src = ei;
    const int* dst = ei + e;

    float *y, *z, *h, *y2;
    int* cnt;
    cudaGetSymbolAddress((void**)&y,   g_y);
    cudaGetSymbolAddress((void**)&z,   g_z);
    cudaGetSymbolAddress((void**)&h,   g_h);
    cudaGetSymbolAddress((void**)&y2,  g_y2);
    cudaGetSymbolAddress((void**)&cnt, g_cnt);

    const int TB = 256;

    // build
    cudaMemsetAsync(cnt, 0, (size_t)n * sizeof(int));
    k_place<<<(e + TB - 1) / TB, TB>>>(src, dst, e);

    // layer 1
    k_prescale<<<(n * 16 + TB - 1) / TB, TB>>>(x, y, n);
    k_agg<false><<<(n + 31) / 32, dim3(16, 32)>>>(y, z, nullptr, n);
    k_gemm1<<<(n + 47) / 48, dim3(32, 8)>>>(z, W1, b1, h, n);

    // layer 2
    k_gemm2<<<(n + 95) / 96, dim3(16, 16)>>>(h, W2, y2, n);
    k_agg<true><<<(n + 31) / 32, dim3(16, 32)>>>(y2, out, b2, n);
}

// round 16
// speedup vs baseline: 1.1305x; 1.1305x over previous
#include <cuda_runtime.h>

// 2-layer GCN: R13 agg/prescale/build + FUSED gemm1+gemm2 (h staged in dynamic smem).

#define N_NODES 50000
#define DIM_IN 64
#define DIM_HID 128
#define CAP 128
#define HS_STRIDE 132   // 128 + 4 pad

// dynamic smem layout (floats): W1s [64*128] | W2s [128*64] | Hs [64*HS_STRIDE]
#define SM_W1 0
#define SM_W2 (64 * 128)
#define SM_HS (64 * 128 + 128 * 64)
#define SM_TOTAL_FLOATS (64 * 128 + 128 * 64 + 64 * HS_STRIDE)

typedef unsigned long long u64;

__device__ __forceinline__ u64 pk(float v) {
    u64 r; asm("mov.b64 %0, {%1, %1};" : "=l"(r) : "f"(v)); return r;
}
__device__ __forceinline__ void fma2(u64& d, u64 a, u64 b) {
    asm("fma.rn.f32x2 %0, %1, %2, %3;" : "=l"(d) : "l"(a), "l"(b), "l"(d));
}
__device__ __forceinline__ float2 up(u64 v) {
    float2 f; asm("mov.b64 {%0, %1}, %2;" : "=f"(f.x), "=f"(f.y) : "l"(v)); return f;
}

__device__ int   g_cnt[N_NODES];
__device__ int   g_bucket[N_NODES * CAP];
__device__ float g_dinv[N_NODES];
__device__ float g_y   [N_NODES * DIM_IN];
__device__ float g_z   [N_NODES * DIM_IN];
__device__ float g_y2  [N_NODES * DIM_IN];

// ---------------- build ----------------
__global__ void k_place(const int* __restrict__ src, const int* __restrict__ dst, int e) {
    int i = blockIdx.x * blockDim.x + threadIdx.x;
    if (i < e) {
        int d = dst[i];
        int pos = atomicAdd(&g_cnt[d], 1);
        g_bucket[d * CAP + pos] = src[i];
    }
}

// ---------------- prescale: y = dinv*x ; materialize dinv ----------------
__global__ void k_prescale(const float* __restrict__ x, float* __restrict__ y, int n) {
    int idx = blockIdx.x * blockDim.x + threadIdx.x;  // n*16
    if (idx >= n * 16) return;
    int i = idx >> 4;
    float d = rsqrtf((float)g_cnt[i] + 1.0f);
    if ((idx & 15) == 0) g_dinv[i] = d;
    float4 v = reinterpret_cast<const float4*>(x)[idx];
    float4 o = {d * v.x, d * v.y, d * v.z, d * v.w};
    reinterpret_cast<float4*>(y)[idx] = o;
}

// ---------------- gather aggregation (R5 core) ----------------
template <bool FINISH>
__global__ void __launch_bounds__(512, 3) k_agg(
        const float* __restrict__ F, float* __restrict__ O,
        const float* __restrict__ bias, int n) {
    int node = blockIdx.x * 32 + threadIdx.y;
    if (node >= n) return;
    int lane = threadIdx.x;
    const float4* F4 = reinterpret_cast<const float4*>(F);
    const int4* cols4 = reinterpret_cast<const int4*>(g_bucket + node * CAP);
    int cnt = g_cnt[node];

    float4 acc = F4[node * 16 + lane];  // self term
    int j = 0;
    for (; j + 4 <= cnt; j += 4) {
        int4 c = __ldg(&cols4[j >> 2]);
        float4 u0 = F4[c.x * 16 + lane];
        float4 u1 = F4[c.y * 16 + lane];
        float4 u2 = F4[c.z * 16 + lane];
        float4 u3 = F4[c.w * 16 + lane];
        acc.x += (u0.x + u1.x) + (u2.x + u3.x);
        acc.y += (u0.y + u1.y) + (u2.y + u3.y);
        acc.z += (u0.z + u1.z) + (u2.z + u3.z);
        acc.w += (u0.w + u1.w) + (u2.w + u3.w);
    }
    if (j < cnt) {
        int4 c = __ldg(&cols4[j >> 2]);
        int rem = cnt - j;
        float4 u0 = F4[c.x * 16 + lane];
        acc.x += u0.x; acc.y += u0.y; acc.z += u0.z; acc.w += u0.w;
        if (rem > 1) {
            float4 u1 = F4[c.y * 16 + lane];
            acc.x += u1.x; acc.y += u1.y; acc.z += u1.z; acc.w += u1.w;
        }
        if (rem > 2) {
            float4 u2 = F4[c.z * 16 + lane];
            acc.x += u2.x; acc.y += u2.y; acc.z += u2.z; acc.w += u2.w;
        }
    }
    float4 o;
    if (FINISH) {
        float di = g_dinv[node];
        float4 bb = reinterpret_cast<const float4*>(bias)[lane];
        o.x = fmaf(di, acc.x, bb.x);
        o.y = fmaf(di, acc.y, bb.y);
        o.z = fmaf(di, acc.z, bb.z);
        o.w = fmaf(di, acc.w, bb.w);
    } else {
        o = acc;
    }
    reinterpret_cast<float4*>(O)[node * 16 + lane] = o;
}

// ---------------- FUSED MLP: y2 = dinv*(relu(b1 + dinv*(z@W1)) @ W2) ----------------
// 256 threads, 64 rows/block. Dynamic smem ~97.3 KB.
__global__ void __launch_bounds__(256) k_mlp(
        const float* __restrict__ Z, const float* __restrict__ W1,
        const float* __restrict__ b1, const float* __restrict__ W2,
        float* __restrict__ Y2, int n) {
    extern __shared__ float sm[];
    float* W1s = sm + SM_W1;
    float* W2s = sm + SM_W2;
    float* Hs  = sm + SM_HS;
    int tid = threadIdx.x;
    {
        const float4* w14 = reinterpret_cast<const float4*>(W1);
        const float4* w24 = reinterpret_cast<const float4*>(W2);
        float4* s14 = reinterpret_cast<float4*>(W1s);
        float4* s24 = reinterpret_cast<float4*>(W2s);
        for (int i = tid; i < 64 * 128 / 4; i += 256) {
            s14[i] = w14[i];
            s24[i] = w24[i];
        }
    }
    __syncthreads();
    int blk_r0 = blockIdx.x * 64;

    // ---------- stage 1: h tile (32 col-threads x 8 row-threads, 8 rows each) ----------
    {
        int tx = tid & 31;
        int ty = tid >> 5;
        int r0 = blk_r0 + ty * 8;
        int rr[8];
        #pragma unroll
        for (int q = 0; q < 8; q++) rr[q] = min(r0 + q, n - 1);
        const float4* A4 = reinterpret_cast<const float4*>(Z);
        const ulonglong2* ws2 = reinterpret_cast<const ulonglong2*>(W1s);
        u64 acc[8][2] = {};
        #pragma unroll
        for (int k4 = 0; k4 < 16; k4++) {
            float va[8][4];
            #pragma unroll
            for (int q = 0; q < 8; q++) {
                float4 v = A4[rr[q] * 16 + k4];
                va[q][0] = v.x; va[q][1] = v.y; va[q][2] = v.z; va[q][3] = v.w;
            }
            #pragma unroll
            for (int s = 0; s < 4; s++) {
                ulonglong2 w = ws2[(4 * k4 + s) * 32 + tx];
                #pragma unroll
                for (int q = 0; q < 8; q++) {
                    u64 m = pk(va[q][s]);
                    fma2(acc[q][0], m, w.x);
                    fma2(acc[q][1], m, w.y);
                }
            }
        }
        float4 bb = reinterpret_cast<const float4*>(b1)[tx];
        #pragma unroll
        for (int q = 0; q < 8; q++) {
            float s = g_dinv[rr[q]];
            float2 lo = up(acc[q][0]);
            float2 hi = up(acc[q][1]);
            float* hrow = &Hs[(ty * 8 + q) * HS_STRIDE + tx * 4];
            hrow[0] = fmaxf(fmaf(s, lo.x, bb.x), 0.f);
            hrow[1] = fmaxf(fmaf(s, lo.y, bb.y), 0.f);
            hrow[2] = fmaxf(fmaf(s, hi.x, bb.z), 0.f);
            hrow[3] = fmaxf(fmaf(s, hi.y, bb.w), 0.f);
        }
    }
    __syncthreads();

    // ---------- stage 2: y2 from smem h (16 col-threads x 16 row-threads, 4 rows each) ----------
    {
        int tx = tid & 15;
        int ty = tid >> 4;
        int r0 = blk_r0 + ty * 4;
        const ulonglong2* ws2 = reinterpret_cast<const ulonglong2*>(W2s);
        u64 acc[4][2] = {};
        #pragma unroll
        for (int k4 = 0; k4 < 32; k4++) {
            float va[4][4];
            #pragma unroll
            for (int q = 0; q < 4; q++) {
                const float4* hrow = reinterpret_cast<const float4*>(&Hs[(ty * 4 + q) * HS_STRIDE]);
                float4 v = hrow[k4];
                va[q][0] = v.x; va[q][1] = v.y; va[q][2] = v.z; va[q][3] = v.w;
            }
            #pragma unroll
            for (int s = 0; s < 4; s++) {
                ulonglong2 w = ws2[(4 * k4 + s) * 16 + tx];
                #pragma unroll
                for (int q = 0; q < 4; q++) {
                    u64 m = pk(va[q][s]);
                    fma2(acc[q][0], m, w.x);
                    fma2(acc[q][1], m, w.y);
                }
            }
        }
        float4* Y4 = reinterpret_cast<float4*>(Y2);
        #pragma unroll
        for (int q = 0; q < 4; q++) {
            int r = r0 + q;
            if (r < n) {
                float s = g_dinv[r];
                float2 lo = up(acc[q][0]);
                float2 hi = up(acc[q][1]);
                float4 o = {s * lo.x, s * lo.y, s * hi.x, s * hi.y};
                Y4[(size_t)r * 16 + tx] = o;
            }
        }
    }
}

extern "C" void kernel_launch(void* const* d_in, const int* in_sizes, int n_in,
                              void* d_out, int out_size) {
    const float* x  = (const float*)d_in[0];
    const int*   ei = (const int*)  d_in[1];
    const float* W1 = (const float*)d_in[2];
    const float* b1 = (const float*)d_in[3];
    const float* W2 = (const float*)d_in[4];
    const float* b2 = (const float*)d_in[5];
    float* out = (float*)d_out;

    int n = in_sizes[0] / DIM_IN;   // 50000
    int e = in_sizes[1] / 2;        // 800000
    const int* src = ei;
    const int* dst = ei + e;

    float *y, *z, *y2;
    int* cnt;
    cudaGetSymbolAddress((void**)&y,   g_y);
    cudaGetSymbolAddress((void**)&z,   g_z);
    cudaGetSymbolAddress((void**)&y2,  g_y2);
    cudaGetSymbolAddress((void**)&cnt, g_cnt);

    const int TB = 256;
    const int MLP_SMEM = SM_TOTAL_FLOATS * (int)sizeof(float);   // ~97.3 KB

    static bool attr_set = false;
    if (!attr_set) {
        cudaFuncSetAttribute(k_mlp, cudaFuncAttributeMaxDynamicSharedMemorySize, MLP_SMEM);
        attr_set = true;
    }

    // build
    cudaMemsetAsync(cnt, 0, (size_t)n * sizeof(int));
    k_place<<<(e + TB - 1) / TB, TB>>>(src, dst, e);

    // layer 1 aggregation
    k_prescale<<<(n * 16 + TB - 1) / TB, TB>>>(x, y, n);
    k_agg<false><<<(n + 31) / 32, dim3(16, 32)>>>(y, z, nullptr, n);

    // fused MLP (gemm1 + relu + gemm2)
    k_mlp<<<(n + 63) / 64, 256, MLP_SMEM>>>(z, W1, b1, W2, y2, n);

    // layer 2 aggregation
    k_agg<true><<<(n + 31) / 32, dim3(16, 32)>>>(y2, out, b2, n);
}

// round 17
// speedup vs baseline: 1.1724x; 1.0370x over previous
#include <cuda_runtime.h>

// 2-layer GCN: R16 + smem-staged Z in k_mlp, Hs aliased over dead W1s/Zs regions.

#define N_NODES 50000
#define DIM_IN 64
#define DIM_HID 128
#define CAP 128
#define HS_STRIDE 132

// dynamic smem (floats): [W2s 8192][W1s 8192][Zs 4096] = 20480 floats = 80 KB
// Hs (64*HS_STRIDE = 8448 floats) aliases offset 8192.. (W1s+Zs, dead after stage 1)
#define SM_W2 0
#define SM_W1 8192
#define SM_ZS (8192 + 8192)
#define SM_HS 8192
#define SM_TOTAL_FLOATS 20480

typedef unsigned long long u64;

__device__ __forceinline__ u64 pk(float v) {
    u64 r; asm("mov.b64 %0, {%1, %1};" : "=l"(r) : "f"(v)); return r;
}
__device__ __forceinline__ void fma2(u64& d, u64 a, u64 b) {
    asm("fma.rn.f32x2 %0, %1, %2, %3;" : "=l"(d) : "l"(a), "l"(b), "l"(d));
}
__device__ __forceinline__ float2 up(u64 v) {
    float2 f; asm("mov.b64 {%0, %1}, %2;" : "=f"(f.x), "=f"(f.y) : "l"(v)); return f;
}

__device__ int   g_cnt[N_NODES];
__device__ int   g_bucket[N_NODES * CAP];
__device__ float g_dinv[N_NODES];
__device__ float g_y   [N_NODES * DIM_IN];
__device__ float g_z   [N_NODES * DIM_IN];
__device__ float g_y2  [N_NODES * DIM_IN];

// ---------------- build ----------------
__global__ void k_place(const int* __restrict__ src, const int* __restrict__ dst, int e) {
    int i = blockIdx.x * blockDim.x + threadIdx.x;
    if (i < e) {
        int d = dst[i];
        int pos = atomicAdd(&g_cnt[d], 1);
        g_bucket[d * CAP + pos] = src[i];
    }
}

// ---------------- prescale: y = dinv*x ; materialize dinv ----------------
__global__ void k_prescale(const float* __restrict__ x, float* __restrict__ y, int n) {
    int idx = blockIdx.x * blockDim.x + threadIdx.x;  // n*16
    if (idx >= n * 16) return;
    int i = idx >> 4;
    float d = rsqrtf((float)g_cnt[i] + 1.0f);
    if ((idx & 15) == 0) g_dinv[i] = d;
    float4 v = reinterpret_cast<const float4*>(x)[idx];
    float4 o = {d * v.x, d * v.y, d * v.z, d * v.w};
    reinterpret_cast<float4*>(y)[idx] = o;
}

// ---------------- gather aggregation (R5 core) ----------------
template <bool FINISH>
__global__ void __launch_bounds__(512, 3) k_agg(
        const float* __restrict__ F, float* __restrict__ O,
        const float* __restrict__ bias, int n) {
    int node = blockIdx.x * 32 + threadIdx.y;
    if (node >= n) return;
    int lane = threadIdx.x;
    const float4* F4 = reinterpret_cast<const float4*>(F);
    const int4* cols4 = reinterpret_cast<const int4*>(g_bucket + node * CAP);
    int cnt = g_cnt[node];

    float4 acc = F4[node * 16 + lane];  // self term
    int j = 0;
    for (; j + 4 <= cnt; j += 4) {
        int4 c = __ldg(&cols4[j >> 2]);
        float4 u0 = F4[c.x * 16 + lane];
        float4 u1 = F4[c.y * 16 + lane];
        float4 u2 = F4[c.z * 16 + lane];
        float4 u3 = F4[c.w * 16 + lane];
        acc.x += (u0.x + u1.x) + (u2.x + u3.x);
        acc.y += (u0.y + u1.y) + (u2.y + u3.y);
        acc.z += (u0.z + u1.z) + (u2.z + u3.z);
        acc.w += (u0.w + u1.w) + (u2.w + u3.w);
    }
    if (j < cnt) {
        int4 c = __ldg(&cols4[j >> 2]);
        int rem = cnt - j;
        float4 u0 = F4[c.x * 16 + lane];
        acc.x += u0.x; acc.y += u0.y; acc.z += u0.z; acc.w += u0.w;
        if (rem > 1) {
            float4 u1 = F4[c.y * 16 + lane];
            acc.x += u1.x; acc.y += u1.y; acc.z += u1.z; acc.w += u1.w;
        }
        if (rem > 2) {
            float4 u2 = F4[c.z * 16 + lane];
            acc.x += u2.x; acc.y += u2.y; acc.z += u2.z; acc.w += u2.w;
        }
    }
    float4 o;
    if (FINISH) {
        float di = g_dinv[node];
        float4 bb = reinterpret_cast<const float4*>(bias)[lane];
        o.x = fmaf(di, acc.x, bb.x);
        o.y = fmaf(di, acc.y, bb.y);
        o.z = fmaf(di, acc.z, bb.z);
        o.w = fmaf(di, acc.w, bb.w);
    } else {
        o = acc;
    }
    reinterpret_cast<float4*>(O)[node * 16 + lane] = o;
}

// ---------------- FUSED MLP: y2 = dinv*(relu(b1 + dinv*(z@W1)) @ W2) ----------------
// 256 threads, 64 rows/block. Z staged in smem; Hs aliases W1s/Zs after stage 1.
__global__ void __launch_bounds__(256) k_mlp(
        const float* __restrict__ Z, const float* __restrict__ W1,
        const float* __restrict__ b1, const float* __restrict__ W2,
        float* __restrict__ Y2, int n) {
    extern __shared__ float sm[];
    float* W2s = sm + SM_W2;
    float* W1s = sm + SM_W1;
    float* Zs  = sm + SM_ZS;
    float* Hs  = sm + SM_HS;
    int tid = threadIdx.x;
    int blk_r0 = blockIdx.x * 64;
    {
        const float4* w14 = reinterpret_cast<const float4*>(W1);
        const float4* w24 = reinterpret_cast<const float4*>(W2);
        float4* s14 = reinterpret_cast<float4*>(W1s);
        float4* s24 = reinterpret_cast<float4*>(W2s);
        for (int i = tid; i < 64 * 128 / 4; i += 256) {
            s14[i] = w14[i];
            s24[i] = w24[i];
        }
        // Z tile: 64 rows x 16 float4, coalesced (clamp rows for last block)
        const float4* Z4 = reinterpret_cast<const float4*>(Z);
        float4* zs4 = reinterpret_cast<float4*>(Zs);
        for (int i = tid; i < 64 * 16; i += 256) {
            int r = min(blk_r0 + (i >> 4), n - 1);
            zs4[i] = Z4[(size_t)r * 16 + (i & 15)];
        }
    }
    __syncthreads();

    // ---------- stage 1: h into registers (32 col-threads x 8 row-threads, 8 rows each) ----------
    int tx1 = tid & 31;
    int ty1 = tid >> 5;
    u64 acc1[8][2] = {};
    {
        const float4* Zs4 = reinterpret_cast<const float4*>(Zs);
        const ulonglong2* ws2 = reinterpret_cast<const ulonglong2*>(W1s);
        #pragma unroll
        for (int k4 = 0; k4 < 16; k4++) {
            float va[8][4];
            #pragma unroll
            for (int q = 0; q < 8; q++) {
                float4 v = Zs4[(ty1 * 8 + q) * 16 + k4];   // warp broadcast
                va[q][0] = v.x; va[q][1] = v.y; va[q][2] = v.z; va[q][3] = v.w;
            }
            #pragma unroll
            for (int s = 0; s < 4; s++) {
                ulonglong2 w = ws2[(4 * k4 + s) * 32 + tx1];
                #pragma unroll
                for (int q = 0; q < 8; q++) {
                    u64 m = pk(va[q][s]);
                    fma2(acc1[q][0], m, w.x);
                    fma2(acc1[q][1], m, w.y);
                }
            }
        }
    }
    // finalize h in registers (W1s/Zs still live for other warps until barrier)
    float hreg[8][4];
    {
        float4 bb = reinterpret_cast<const float4*>(b1)[tx1];
        #pragma unroll
        for (int q = 0; q < 8; q++) {
            int r = min(blk_r0 + ty1 * 8 + q, n - 1);
            float s = g_dinv[r];
            float2 lo = up(acc1[q][0]);
            float2 hi = up(acc1[q][1]);
            hreg[q][0] = fmaxf(fmaf(s, lo.x, bb.x), 0.f);
            hreg[q][1] = fmaxf(fmaf(s, lo.y, bb.y), 0.f);
            hreg[q][2] = fmaxf(fmaf(s, hi.x, bb.z), 0.f);
            hreg[q][3] = fmaxf(fmaf(s, hi.y, bb.w), 0.f);
        }
    }
    __syncthreads();   // all reads of W1s/Zs done -> safe to overwrite with Hs
    #pragma unroll
    for (int q = 0; q < 8; q++) {
        float* hrow = &Hs[(ty1 * 8 + q) * HS_STRIDE + tx1 * 4];
        hrow[0] = hreg[q][0];
        hrow[1] = hreg[q][1];
        hrow[2] = hreg[q][2];
        hrow[3] = hreg[q][3];
    }
    __syncthreads();

    // ---------- stage 2: y2 from smem h (16 col-threads x 16 row-threads, 4 rows each) ----------
    {
        int tx = tid & 15;
        int ty = tid >> 4;
        int r0 = blk_r0 + ty * 4;
        const ulonglong2* ws2 = reinterpret_cast<const ulonglong2*>(W2s);
        u64 acc[4][2] = {};
        #pragma unroll
        for (int k4 = 0; k4 < 32; k4++) {
            float va[4][4];
            #pragma unroll
            for (int q = 0; q < 4; q++) {
                const float4* hrow = reinterpret_cast<const float4*>(&Hs[(ty * 4 + q) * HS_STRIDE]);
                float4 v = hrow[k4];
                va[q][0] = v.x; va[q][1] = v.y; va[q][2] = v.z; va[q][3] = v.w;
            }
            #pragma unroll
            for (int s = 0; s < 4; s++) {
                ulonglong2 w = ws2[(4 * k4 + s) * 16 + tx];
                #pragma unroll
                for (int q = 0; q < 4; q++) {
                    u64 m = pk(va[q][s]);
                    fma2(acc[q][0], m, w.x);
                    fma2(acc[q][1], m, w.y);
                }
            }
        }
        float4* Y4 = reinterpret_cast<float4*>(Y2);
        #pragma unroll
        for (int q = 0; q < 4; q++) {
            int r = r0 + q;
            if (r < n) {
                float s = g_dinv[r];
                float2 lo = up(acc[q][0]);
                float2 hi = up(acc[q][1]);
                float4 o = {s * lo.x, s * lo.y, s * hi.x, s * hi.y};
                Y4[(size_t)r * 16 + tx] = o;
            }
        }
    }
}

extern "C" void kernel_launch(void* const* d_in, const int* in_sizes, int n_in,
                              void* d_out, int out_size) {
    const float* x  = (const float*)d_in[0];
    const int*   ei = (const int*)  d_in[1];
    const float* W1 = (const float*)d_in[2];
    const float* b1 = (const float*)d_in[3];
    const float* W2 = (const float*)d_in[4];
    const float* b2 = (const float*)d_in[5];
    float* out = (float*)d_out;

    int n = in_sizes[0] / DIM_IN;   // 50000
    int e = in_sizes[1] / 2;        // 800000
    const int* src = ei;
    const int* dst = ei + e;

    float *y, *z, *y2;
    int* cnt;
    cudaGetSymbolAddress((void**)&y,   g_y);
    cudaGetSymbolAddress((void**)&z,   g_z);
    cudaGetSymbolAddress((void**)&y2,  g_y2);
    cudaGetSymbolAddress((void**)&cnt, g_cnt);

    const int TB = 256;
    const int MLP_SMEM = SM_TOTAL_FLOATS * (int)sizeof(float);   // 80 KB

    cudaFuncSetAttribute(k_mlp, cudaFuncAttributeMaxDynamicSharedMemorySize, MLP_SMEM);

    // build
    cudaMemsetAsync(cnt, 0, (size_t)n * sizeof(int));
    k_place<<<(e + TB - 1) / TB, TB>>>(src, dst, e);

    // layer 1 aggregation
    k_prescale<<<(n * 16 + TB - 1) / TB, TB>>>(x, y, n);
    k_agg<false><<<(n + 31) / 32, dim3(16, 32)>>>(y, z, nullptr, n);

    // fused MLP (gemm1 + relu + gemm2)
    k_mlp<<<(n + 63) / 64, 256, MLP_SMEM>>>(z, W1, b1, W2, y2, n);

    // layer 2 aggregation
    k_agg<true><<<(n + 31) / 32, dim3(16, 32)>>>(y2, out, b2, n);
}